// round 1
// baseline (speedup 1.0000x reference)
#include <cuda_runtime.h>

// Bahdanau attention, B200 baseline.
// Sizes fixed by the problem:
#define NB 32
#define NS 4096
#define ND 512
#define NU 512

#define BM 128
#define BN 128
#define BK 16

// Scratch (device globals: no allocations allowed in kernel_launch)
__device__ float g_score[NB * NS];          // [B,S] pre-softmax scores
__device__ float g_decp[NB * NU];           // dec@W2 + b1 + b2 (fused bias)
__device__ float g_ctx_part[32 * NB * ND];  // partial context sums [chunk][B][D]

// ---------------------------------------------------------------------------
// K0: initialize scores to bv (atomic partials accumulate on top)
// ---------------------------------------------------------------------------
__global__ void init_score_kernel(const float* __restrict__ bv) {
    int i = blockIdx.x * blockDim.x + threadIdx.x;
    if (i < NB * NS) g_score[i] = bv[0];
}

// ---------------------------------------------------------------------------
// K1: g_decp[b,u] = sum_d dec[b,d]*W2[d,u] + b1[u] + b2[u]
// ---------------------------------------------------------------------------
__global__ void decp_kernel(const float* __restrict__ dec,
                            const float* __restrict__ W2,
                            const float* __restrict__ b1,
                            const float* __restrict__ b2) {
    int b = blockIdx.x;
    int u = threadIdx.x;
    __shared__ float ds[ND];
    ds[u] = dec[b * ND + u];
    __syncthreads();
    float acc = b1[u] + b2[u];
#pragma unroll 8
    for (int d = 0; d < ND; d++) acc += ds[d] * W2[d * NU + u];
    g_decp[b * NU + u] = acc;
}

// ---------------------------------------------------------------------------
// K2: fused GEMM + tanh + V-dot -> atomic partial into g_score[b,s]
//   A = encoder_output rows [M=B*S, K=D], Bmat = W1 [K=D, N=U]
//   Tile 128x128x16, 256 threads, 8x8 microtile per thread.
//   Each 128-row tile lies inside a single batch (S=4096 % 128 == 0).
// ---------------------------------------------------------------------------
__global__ __launch_bounds__(256, 2)
void score_gemm_kernel(const float* __restrict__ enc,
                       const float* __restrict__ W1,
                       const float* __restrict__ V) {
    __shared__ float As[BK][BM];  // transposed A tile
    __shared__ float Bs[BK][BN];

    const int tid = threadIdx.x;
    const int by = blockIdx.x;          // row tile (0..1023)
    const int bx = blockIdx.y;          // col tile (0..3)
    const int rowBase = by * BM;
    const int colBase = bx * BN;
    const int b = rowBase / NS;         // batch index, constant per block

    const int tx = tid & 15;            // 0..15 -> 8 cols each
    const int ty = tid >> 4;            // 0..15 -> 8 rows each

    // global-load indices
    const int arow  = tid >> 2;          // 0..63 (two passes of 64 rows)
    const int acol4 = (tid & 3) * 4;     // 0,4,8,12 within BK
    const int brow  = tid >> 5;          // 0..7  (two passes of 8 k-rows)
    const int bcol4 = (tid & 31) * 4;    // 0..124

    const float* Abase = enc + (size_t)rowBase * ND;

    float c[8][8];
#pragma unroll
    for (int i = 0; i < 8; i++)
#pragma unroll
        for (int j = 0; j < 8; j++) c[i][j] = 0.f;

    for (int k0 = 0; k0 < ND; k0 += BK) {
#pragma unroll
        for (int p = 0; p < 2; p++) {
            int r = arow + p * 64;
            float4 v = *(const float4*)(Abase + (size_t)r * ND + k0 + acol4);
            As[acol4 + 0][r] = v.x;
            As[acol4 + 1][r] = v.y;
            As[acol4 + 2][r] = v.z;
            As[acol4 + 3][r] = v.w;
        }
#pragma unroll
        for (int p = 0; p < 2; p++) {
            int r = brow + p * 8;
            float4 v = *(const float4*)(W1 + (size_t)(k0 + r) * NU + colBase + bcol4);
            *(float4*)&Bs[r][bcol4] = v;
        }
        __syncthreads();

#pragma unroll
        for (int k = 0; k < BK; k++) {
            float a[8], bb[8];
            *(float4*)&a[0]  = *(const float4*)&As[k][ty * 8];
            *(float4*)&a[4]  = *(const float4*)&As[k][ty * 8 + 4];
            *(float4*)&bb[0] = *(const float4*)&Bs[k][tx * 8];
            *(float4*)&bb[4] = *(const float4*)&Bs[k][tx * 8 + 4];
#pragma unroll
            for (int i = 0; i < 8; i++)
#pragma unroll
                for (int j = 0; j < 8; j++) c[i][j] += a[i] * bb[j];
        }
        __syncthreads();
    }

    // Epilogue: score partial = sum_j tanh(c + decp[b,col]) * V[col]
    float dv[8], vv[8];
#pragma unroll
    for (int j = 0; j < 8; j++) {
        int col = colBase + tx * 8 + j;
        dv[j] = g_decp[b * NU + col];
        vv[j] = V[col];
    }
    float partial[8];
#pragma unroll
    for (int i = 0; i < 8; i++) {
        float p = 0.f;
#pragma unroll
        for (int j = 0; j < 8; j++) p += tanhf(c[i][j] + dv[j]) * vv[j];
        partial[i] = p;
    }

    // In-block reduction across the 16 column-thread groups (reuse As as smem)
    float* red = &As[0][0];  // 2048 floats available
#pragma unroll
    for (int i = 0; i < 8; i++) red[(ty * 8 + i) * 16 + tx] = partial[i];
    __syncthreads();
    if (tid < BM) {
        float s = 0.f;
#pragma unroll
        for (int t = 0; t < 16; t++) s += red[tid * 16 + t];
        atomicAdd(&g_score[rowBase + tid], s);
    }
}

// ---------------------------------------------------------------------------
// K3: softmax over S per batch; writes attention weights into d_out[B*D ...]
// ---------------------------------------------------------------------------
__global__ void softmax_kernel(float* __restrict__ out) {
    const int b = blockIdx.x;
    const int t = threadIdx.x;  // 1024 threads, 4 elements each
    const float* sc = g_score + b * NS;

    __shared__ float redbuf[32];
    __shared__ float s_max, s_sum;

    float v[4];
    float m = -3.4e38f;
#pragma unroll
    for (int i = 0; i < 4; i++) {
        v[i] = sc[t + i * 1024];
        m = fmaxf(m, v[i]);
    }
#pragma unroll
    for (int o = 16; o > 0; o >>= 1) m = fmaxf(m, __shfl_xor_sync(0xffffffffu, m, o));
    if ((t & 31) == 0) redbuf[t >> 5] = m;
    __syncthreads();
    if (t < 32) {
        float x = redbuf[t];
#pragma unroll
        for (int o = 16; o > 0; o >>= 1) x = fmaxf(x, __shfl_xor_sync(0xffffffffu, x, o));
        if (t == 0) s_max = x;
    }
    __syncthreads();
    const float bm = s_max;

    float e[4];
    float s = 0.f;
#pragma unroll
    for (int i = 0; i < 4; i++) {
        e[i] = __expf(v[i] - bm);
        s += e[i];
    }
#pragma unroll
    for (int o = 16; o > 0; o >>= 1) s += __shfl_xor_sync(0xffffffffu, s, o);
    if ((t & 31) == 0) redbuf[t >> 5] = s;
    __syncthreads();
    if (t < 32) {
        float x = redbuf[t];
#pragma unroll
        for (int o = 16; o > 0; o >>= 1) x += __shfl_xor_sync(0xffffffffu, x, o);
        if (t == 0) s_sum = x;
    }
    __syncthreads();
    const float inv = 1.0f / s_sum;
#pragma unroll
    for (int i = 0; i < 4; i++) out[NB * ND + b * NS + t + i * 1024] = e[i] * inv;
}

// ---------------------------------------------------------------------------
// K4: partial context sums. Grid = B*32 blocks, each handles 128 s-positions.
// ---------------------------------------------------------------------------
__global__ void ctx_part_kernel(const float* __restrict__ enc,
                                const float* __restrict__ out) {
    const int b = blockIdx.x >> 5;
    const int chunk = blockIdx.x & 31;
    const int d = threadIdx.x;  // 512 threads

    __shared__ float ws[128];
    const float* w = out + NB * ND + b * NS + chunk * 128;
    if (d < 128) ws[d] = w[d];
    __syncthreads();

    const float* ep = enc + ((size_t)(b * NS + chunk * 128)) * ND + d;
    float acc = 0.f;
#pragma unroll 8
    for (int s = 0; s < 128; s++) acc += ws[s] * ep[(size_t)s * ND];
    g_ctx_part[((size_t)chunk * NB + b) * ND + d] = acc;
}

// ---------------------------------------------------------------------------
// K5: reduce the 32 partials -> context vector at d_out[0 .. B*D)
// ---------------------------------------------------------------------------
__global__ void ctx_reduce_kernel(float* __restrict__ out) {
    const int b = blockIdx.x;
    const int d = threadIdx.x;
    float acc = 0.f;
#pragma unroll
    for (int c = 0; c < 32; c++) acc += g_ctx_part[((size_t)c * NB + b) * ND + d];
    out[b * ND + d] = acc;
}

// ---------------------------------------------------------------------------
extern "C" void kernel_launch(void* const* d_in, const int* in_sizes, int n_in,
                              void* d_out, int out_size) {
    const float* enc = (const float*)d_in[0];  // [B,S,D]
    const float* dec = (const float*)d_in[1];  // [B,D]
    const float* W1  = (const float*)d_in[2];  // [D,U]
    const float* b1  = (const float*)d_in[3];  // [U]
    const float* W2  = (const float*)d_in[4];  // [D,U]
    const float* b2  = (const float*)d_in[5];  // [U]
    const float* V   = (const float*)d_in[6];  // [U,1]
    const float* bv  = (const float*)d_in[7];  // [1]
    float* out = (float*)d_out;                // [B*D context][B*S weights]

    init_score_kernel<<<(NB * NS + 255) / 256, 256>>>(bv);
    decp_kernel<<<NB, NU>>>(dec, W2, b1, b2);
    score_gemm_kernel<<<dim3(NB * NS / BM, NU / BN), 256>>>(enc, W1, V);
    softmax_kernel<<<NB, 1024>>>(out);
    ctx_part_kernel<<<NB * 32, ND>>>(enc, out);
    ctx_reduce_kernel<<<NB, ND>>>(out);
}

// round 4
// speedup vs baseline: 1.5764x; 1.5764x over previous
#include <cuda_runtime.h>
#include <cuda_bf16.h>
#include <cstdint>

#define NB 32
#define NS 4096
#define ND 512
#define NU 512
#define NM (NB * NS)

// ---------------- device scratch ----------------
__device__ float g_score[NB * NS];
__device__ float g_decp[NB * NU];
__device__ float g_ctx_part[32 * NB * ND];
__device__ __nv_bfloat16 g_w1t_hi[NU * ND];   // W1^T [u][d]
__device__ __nv_bfloat16 g_w1t_lo[NU * ND];

// ---------------- helpers ----------------
static __device__ __forceinline__ uint32_t smem_u32(const void* p) {
    uint32_t a;
    asm("{ .reg .u64 t; cvta.to.shared.u64 t, %1; cvt.u32.u64 %0, t; }" : "=r"(a) : "l"(p));
    return a;
}
static __device__ __forceinline__ void ldmx4(uint32_t* r, uint32_t addr) {
    asm volatile("ldmatrix.sync.aligned.m8n8.x4.shared.b16 {%0,%1,%2,%3}, [%4];"
                 : "=r"(r[0]), "=r"(r[1]), "=r"(r[2]), "=r"(r[3]) : "r"(addr));
}
static __device__ __forceinline__ void mma_bf16(float* c, const uint32_t* a, const uint32_t* b) {
    asm volatile(
        "mma.sync.aligned.m16n8k16.row.col.f32.bf16.bf16.f32 "
        "{%0,%1,%2,%3}, {%4,%5,%6,%7}, {%8,%9}, {%0,%1,%2,%3};"
        : "+f"(c[0]), "+f"(c[1]), "+f"(c[2]), "+f"(c[3])
        : "r"(a[0]), "r"(a[1]), "r"(a[2]), "r"(a[3]), "r"(b[0]), "r"(b[1]));
}
static __device__ __forceinline__ uint32_t sw128(uint32_t o) { return o ^ ((o >> 3) & 0x70); }
static __device__ __forceinline__ uint32_t pack2(float x, float y) {
    __nv_bfloat162 t = __floats2bfloat162_rn(x, y);
    return *(uint32_t*)&t;
}
static __device__ __forceinline__ float tanh_fast(float x) {
    float e = __expf(2.0f * x);
    return 1.0f - __fdividef(2.0f, e + 1.0f);
}

// ---------------------------------------------------------------------------
// prepass: W1 [D,U] -> transposed hi/lo bf16 [U][D]
// ---------------------------------------------------------------------------
__global__ void convert_w1_kernel(const float* __restrict__ W1) {
    int i = blockIdx.x * blockDim.x + threadIdx.x;   // u*ND + d
    int u = i >> 9, d = i & 511;
    float x = W1[d * NU + u];
    __nv_bfloat16 h = __float2bfloat16(x);
    g_w1t_hi[i] = h;
    g_w1t_lo[i] = __float2bfloat16(x - __bfloat162float(h));
}

__global__ void init_score_kernel(const float* __restrict__ bv) {
    int i = blockIdx.x * blockDim.x + threadIdx.x;
    if (i < NB * NS) g_score[i] = bv[0];
}

__global__ void decp_kernel(const float* __restrict__ dec, const float* __restrict__ W2,
                            const float* __restrict__ b1, const float* __restrict__ b2) {
    int b = blockIdx.x, u = threadIdx.x;
    __shared__ float ds[ND];
    ds[u] = dec[b * ND + u];
    __syncthreads();
    float acc = b1[u] + b2[u];
#pragma unroll 8
    for (int d = 0; d < ND; d++) acc += ds[d] * W2[d * NU + u];
    g_decp[b * NU + u] = acc;
}

// ---------------------------------------------------------------------------
// GEMM via mma.sync bf16 3-term split + tanh + V-dot epilogue.
// CTA tile 128x128, 256 threads (8 warps, warp tile 64x32), k-chunk 64.
// SMEM: Ahi, Alo, Bhi, Blo each 128 rows x 128 bytes, SW128 swizzled.
// ---------------------------------------------------------------------------
#define SMEM_BYTES (4 * 16384)

__global__ __launch_bounds__(256, 2)
void score_gemm_mma(const float* __restrict__ enc, const float* __restrict__ V) {
    extern __shared__ char sm[];
    const uint32_t uAhi = smem_u32(sm);
    const uint32_t uAlo = uAhi + 16384;
    const uint32_t uBhi = uAhi + 32768;
    const uint32_t uBlo = uAhi + 49152;

    const int tid = threadIdx.x;
    const int w = tid >> 5;
    const int lane = tid & 31;
    const int rowBase = blockIdx.x * 128;
    const int colBase = blockIdx.y * 128;
    const int b = rowBase / NS;

    const int wm = (w & 1) * 64;     // warp row offset in tile
    const int wn = (w >> 1) * 32;    // warp col offset in tile

    // ldmatrix lane address components
    const int aKH = (lane >> 4) * 16;              // A: k halves by lane>=16
    const int bKH = ((lane >> 3) & 1) * 16;        // B: k halves by lane bit3
    int rowA[4], xorA[4];
#pragma unroll
    for (int mt = 0; mt < 4; mt++) {
        rowA[mt] = wm + mt * 16 + (lane & 15);
        xorA[mt] = (rowA[mt] & 7) << 4;
    }
    int rowB[2], xorB[2];
#pragma unroll
    for (int nt2 = 0; nt2 < 2; nt2++) {
        rowB[nt2] = wn + nt2 * 16 + (lane & 7) + ((lane >> 4) << 3);
        xorB[nt2] = (rowB[nt2] & 7) << 4;
    }

    float c[4][4][4];
#pragma unroll
    for (int i = 0; i < 4; i++)
#pragma unroll
        for (int j = 0; j < 4; j++)
#pragma unroll
            for (int k = 0; k < 4; k++) c[i][j][k] = 0.f;

    const float* gA = enc + (size_t)rowBase * ND;

    for (int cc = 0; cc < 8; cc++) {
        const int k0 = cc * 64;
        // --- load + split A (fp32 -> bf16 hi/lo), 8 elems per thread-iter ---
#pragma unroll
        for (int it = 0; it < 4; it++) {
            int idx = tid + it * 256;          // 0..1023
            int row = idx >> 3;
            int g = idx & 7;
            const float* src = gA + (size_t)row * ND + k0 + g * 8;
            float4 v0 = *(const float4*)src;
            float4 v1 = *(const float4*)(src + 4);
            uint4 hi, lo;
            hi.x = pack2(v0.x, v0.y); hi.y = pack2(v0.z, v0.w);
            hi.z = pack2(v1.x, v1.y); hi.w = pack2(v1.z, v1.w);
            __nv_bfloat162 h;
            *(uint32_t*)&h = hi.x;
            lo.x = pack2(v0.x - __bfloat162float(h.x), v0.y - __bfloat162float(h.y));
            *(uint32_t*)&h = hi.y;
            lo.y = pack2(v0.z - __bfloat162float(h.x), v0.w - __bfloat162float(h.y));
            *(uint32_t*)&h = hi.z;
            lo.z = pack2(v1.x - __bfloat162float(h.x), v1.y - __bfloat162float(h.y));
            *(uint32_t*)&h = hi.w;
            lo.w = pack2(v1.z - __bfloat162float(h.x), v1.w - __bfloat162float(h.y));
            uint32_t so = sw128(row * 128 + g * 16);
            *(uint4*)(sm + (so)) = hi;                      // uAhi region
            *(uint4*)(sm + 16384 + so) = lo;                // uAlo region
        }
        // --- load B hi/lo (already bf16 in gmem) ---
#pragma unroll
        for (int it = 0; it < 4; it++) {
            int idx = tid + it * 256;
            int row = idx >> 3;
            int g = idx & 7;
            size_t go = (size_t)(colBase + row) * ND + k0 + g * 8;
            uint32_t so = sw128(row * 128 + g * 16);
            *(uint4*)(sm + 32768 + so) = *(const uint4*)(g_w1t_hi + go);
            *(uint4*)(sm + 49152 + so) = *(const uint4*)(g_w1t_lo + go);
        }
        __syncthreads();

        // --- 3 term passes: Ahi*Bhi, Ahi*Blo, Alo*Bhi ---
#pragma unroll
        for (int term = 0; term < 3; term++) {
            const uint32_t uA = (term == 2) ? uAlo : uAhi;
            const uint32_t uB = (term == 1) ? uBlo : uBhi;
#pragma unroll
            for (int s = 0; s < 4; s++) {
                uint32_t af[4][4], bf[2][4];
#pragma unroll
                for (int mt = 0; mt < 4; mt++)
                    ldmx4(af[mt], uA + rowA[mt] * 128 + ((s * 32 + aKH) ^ xorA[mt]));
#pragma unroll
                for (int nt2 = 0; nt2 < 2; nt2++)
                    ldmx4(bf[nt2], uB + rowB[nt2] * 128 + ((s * 32 + bKH) ^ xorB[nt2]));
#pragma unroll
                for (int mt = 0; mt < 4; mt++)
#pragma unroll
                    for (int nt = 0; nt < 4; nt++)
                        mma_bf16(c[mt][nt], af[mt], &bf[nt >> 1][(nt & 1) * 2]);
            }
        }
        __syncthreads();
    }

    // --- epilogue: tanh + V-dot, reduce cols, atomic per row ---
    float dv[8], vv[8];
#pragma unroll
    for (int nt = 0; nt < 4; nt++) {
#pragma unroll
        for (int i = 0; i < 2; i++) {
            int col = colBase + wn + nt * 8 + (lane & 3) * 2 + i;
            dv[nt * 2 + i] = g_decp[b * NU + col];
            vv[nt * 2 + i] = V[col];
        }
    }
    float rowsum[4][2];
#pragma unroll
    for (int mt = 0; mt < 4; mt++) {
#pragma unroll
        for (int h = 0; h < 2; h++) {
            float s = 0.f;
#pragma unroll
            for (int nt = 0; nt < 4; nt++) {
#pragma unroll
                for (int i = 0; i < 2; i++) {
                    float x = c[mt][nt][h * 2 + i] + dv[nt * 2 + i];
                    s += tanh_fast(x) * vv[nt * 2 + i];
                }
            }
            rowsum[mt][h] = s;
        }
    }
    // reduce across the 4 lanes of each row group (lane&3)
#pragma unroll
    for (int mt = 0; mt < 4; mt++) {
#pragma unroll
        for (int h = 0; h < 2; h++) {
            float s = rowsum[mt][h];
            s += __shfl_xor_sync(0xffffffffu, s, 1);
            s += __shfl_xor_sync(0xffffffffu, s, 2);
            rowsum[mt][h] = s;
        }
    }
    if ((lane & 3) == 0) {
#pragma unroll
        for (int mt = 0; mt < 4; mt++)
#pragma unroll
            for (int h = 0; h < 2; h++) {
                int r = rowBase + wm + mt * 16 + (lane >> 2) + h * 8;
                atomicAdd(&g_score[r], rowsum[mt][h]);
            }
    }
}

// ---------------------------------------------------------------------------
__global__ void softmax_kernel(float* __restrict__ out) {
    const int b = blockIdx.x;
    const int t = threadIdx.x;
    const float* sc = g_score + b * NS;
    __shared__ float redbuf[32];
    __shared__ float s_max, s_sum;

    float v[4];
    float m = -3.4e38f;
#pragma unroll
    for (int i = 0; i < 4; i++) { v[i] = sc[t + i * 1024]; m = fmaxf(m, v[i]); }
#pragma unroll
    for (int o = 16; o > 0; o >>= 1) m = fmaxf(m, __shfl_xor_sync(0xffffffffu, m, o));
    if ((t & 31) == 0) redbuf[t >> 5] = m;
    __syncthreads();
    if (t < 32) {
        float x = redbuf[t];
#pragma unroll
        for (int o = 16; o > 0; o >>= 1) x = fmaxf(x, __shfl_xor_sync(0xffffffffu, x, o));
        if (t == 0) s_max = x;
    }
    __syncthreads();
    const float bm = s_max;
    float e[4], s = 0.f;
#pragma unroll
    for (int i = 0; i < 4; i++) { e[i] = __expf(v[i] - bm); s += e[i]; }
#pragma unroll
    for (int o = 16; o > 0; o >>= 1) s += __shfl_xor_sync(0xffffffffu, s, o);
    if ((t & 31) == 0) redbuf[t >> 5] = s;
    __syncthreads();
    if (t < 32) {
        float x = redbuf[t];
#pragma unroll
        for (int o = 16; o > 0; o >>= 1) x += __shfl_xor_sync(0xffffffffu, x, o);
        if (t == 0) s_sum = x;
    }
    __syncthreads();
    const float inv = 1.0f / s_sum;
#pragma unroll
    for (int i = 0; i < 4; i++) out[NB * ND + b * NS + t + i * 1024] = e[i] * inv;
}

__global__ void ctx_part_kernel(const float* __restrict__ enc, const float* __restrict__ out) {
    const int b = blockIdx.x >> 5;
    const int chunk = blockIdx.x & 31;
    const int d = threadIdx.x;
    __shared__ float ws[128];
    const float* w = out + NB * ND + b * NS + chunk * 128;
    if (d < 128) ws[d] = w[d];
    __syncthreads();
    const float* ep = enc + ((size_t)(b * NS + chunk * 128)) * ND + d;
    float acc = 0.f;
#pragma unroll 8
    for (int s = 0; s < 128; s++) acc += ws[s] * ep[(size_t)s * ND];
    g_ctx_part[((size_t)chunk * NB + b) * ND + d] = acc;
}

__global__ void ctx_reduce_kernel(float* __restrict__ out) {
    const int b = blockIdx.x;
    const int d = threadIdx.x;
    float acc = 0.f;
#pragma unroll
    for (int c = 0; c < 32; c++) acc += g_ctx_part[((size_t)c * NB + b) * ND + d];
    out[b * ND + d] = acc;
}

// ---------------------------------------------------------------------------
extern "C" void kernel_launch(void* const* d_in, const int* in_sizes, int n_in,
                              void* d_out, int out_size) {
    const float* enc = (const float*)d_in[0];
    const float* dec = (const float*)d_in[1];
    const float* W1  = (const float*)d_in[2];
    const float* b1  = (const float*)d_in[3];
    const float* W2  = (const float*)d_in[4];
    const float* b2  = (const float*)d_in[5];
    const float* V   = (const float*)d_in[6];
    const float* bv  = (const float*)d_in[7];
    float* out = (float*)d_out;

    cudaFuncSetAttribute(score_gemm_mma, cudaFuncAttributeMaxDynamicSharedMemorySize,
                         SMEM_BYTES);

    convert_w1_kernel<<<NU * ND / 256, 256>>>(W1);
    init_score_kernel<<<(NB * NS + 255) / 256, 256>>>(bv);
    decp_kernel<<<NB, NU>>>(dec, W2, b1, b2);
    score_gemm_mma<<<dim3(NM / 128, NU / 128), 256, SMEM_BYTES>>>(enc, V);
    softmax_kernel<<<NB, 1024>>>(out);
    ctx_part_kernel<<<NB * 32, ND>>>(enc, out);
    ctx_reduce_kernel<<<NB, ND>>>(out);
}

// round 5
// speedup vs baseline: 2.4868x; 1.5775x over previous
#include <cuda_runtime.h>
#include <cuda_bf16.h>
#include <cstdint>

#define NB 32
#define NS 4096
#define ND 512
#define NU 512
#define NM (NB * NS)

// ---------------- device scratch ----------------
__device__ float g_score[NB * NS];
__device__ float g_decp[NB * NU];
__device__ float g_ctx_part[32 * NB * ND];
__device__ __nv_bfloat16 g_enc_hi[(size_t)NM * ND];   // 128 MB
__device__ __nv_bfloat16 g_enc_lo[(size_t)NM * ND];   // 128 MB
__device__ __nv_bfloat16 g_w1t_hi[NU * ND];           // W1^T [u][d]
__device__ __nv_bfloat16 g_w1t_lo[NU * ND];

// ---------------- helpers ----------------
static __device__ __forceinline__ uint32_t smem_u32(const void* p) {
    uint32_t a;
    asm("{ .reg .u64 t; cvta.to.shared.u64 t, %1; cvt.u32.u64 %0, t; }" : "=r"(a) : "l"(p));
    return a;
}
static __device__ __forceinline__ void ldmx4(uint32_t* r, uint32_t addr) {
    asm volatile("ldmatrix.sync.aligned.m8n8.x4.shared.b16 {%0,%1,%2,%3}, [%4];"
                 : "=r"(r[0]), "=r"(r[1]), "=r"(r[2]), "=r"(r[3]) : "r"(addr));
}
static __device__ __forceinline__ void mma_bf16(float* c, const uint32_t* a, const uint32_t* b) {
    asm volatile(
        "mma.sync.aligned.m16n8k16.row.col.f32.bf16.bf16.f32 "
        "{%0,%1,%2,%3}, {%4,%5,%6,%7}, {%8,%9}, {%0,%1,%2,%3};"
        : "+f"(c[0]), "+f"(c[1]), "+f"(c[2]), "+f"(c[3])
        : "r"(a[0]), "r"(a[1]), "r"(a[2]), "r"(a[3]), "r"(b[0]), "r"(b[1]));
}
static __device__ __forceinline__ void cp16(uint32_t s, const void* g) {
    asm volatile("cp.async.cg.shared.global [%0], [%1], 16;" :: "r"(s), "l"(g));
}
#define CP_COMMIT() asm volatile("cp.async.commit_group;" ::: "memory")
#define CP_WAIT1()  asm volatile("cp.async.wait_group 1;" ::: "memory")
#define CP_WAIT0()  asm volatile("cp.async.wait_group 0;" ::: "memory")

static __device__ __forceinline__ uint32_t sw64(uint32_t o) { return o ^ ((o >> 3) & 0x30); }
static __device__ __forceinline__ uint32_t pack2(float x, float y) {
    __nv_bfloat162 t = __floats2bfloat162_rn(x, y);
    return *(uint32_t*)&t;
}
static __device__ __forceinline__ float tanh_fast(float x) {
    float e = __expf(2.0f * x);
    return 1.0f - __fdividef(2.0f, e + 1.0f);
}

// ---------------------------------------------------------------------------
// prepass: enc fp32 -> hi/lo bf16
// ---------------------------------------------------------------------------
__global__ void convert_enc_kernel(const float* __restrict__ enc) {
    size_t i = ((size_t)blockIdx.x * 256 + threadIdx.x) * 8;
    float4 v0 = *(const float4*)(enc + i);
    float4 v1 = *(const float4*)(enc + i + 4);
    uint4 hi, lo;
    hi.x = pack2(v0.x, v0.y); hi.y = pack2(v0.z, v0.w);
    hi.z = pack2(v1.x, v1.y); hi.w = pack2(v1.z, v1.w);
    __nv_bfloat162 h;
    *(uint32_t*)&h = hi.x;
    lo.x = pack2(v0.x - __bfloat162float(h.x), v0.y - __bfloat162float(h.y));
    *(uint32_t*)&h = hi.y;
    lo.y = pack2(v0.z - __bfloat162float(h.x), v0.w - __bfloat162float(h.y));
    *(uint32_t*)&h = hi.z;
    lo.z = pack2(v1.x - __bfloat162float(h.x), v1.y - __bfloat162float(h.y));
    *(uint32_t*)&h = hi.w;
    lo.w = pack2(v1.z - __bfloat162float(h.x), v1.w - __bfloat162float(h.y));
    *(uint4*)(g_enc_hi + i) = hi;
    *(uint4*)(g_enc_lo + i) = lo;
}

// prepass: W1 [D,U] -> transposed hi/lo bf16 [U][D]
__global__ void convert_w1_kernel(const float* __restrict__ W1) {
    int i = blockIdx.x * blockDim.x + threadIdx.x;   // u*ND + d
    int u = i >> 9, d = i & 511;
    float x = W1[d * NU + u];
    __nv_bfloat16 h = __float2bfloat16(x);
    g_w1t_hi[i] = h;
    g_w1t_lo[i] = __float2bfloat16(x - __bfloat162float(h));
}

__global__ void init_score_kernel(const float* __restrict__ bv) {
    int i = blockIdx.x * blockDim.x + threadIdx.x;
    if (i < NB * NS) g_score[i] = bv[0];
}

__global__ void decp_kernel(const float* __restrict__ dec, const float* __restrict__ W2,
                            const float* __restrict__ b1, const float* __restrict__ b2) {
    int b = blockIdx.x, u = threadIdx.x;
    __shared__ float ds[ND];
    ds[u] = dec[b * ND + u];
    __syncthreads();
    float acc = b1[u] + b2[u];
#pragma unroll 8
    for (int d = 0; d < ND; d++) acc += ds[d] * W2[d * NU + u];
    g_decp[b * NU + u] = acc;
}

// ---------------------------------------------------------------------------
// GEMM: mma.sync bf16 3-term split, cp.async 2-stage pipeline, k-chunk 32.
// CTA 128x128, 256 thr (8 warps, warp tile 64x32).
// SMEM per stage: Ahi,Alo,Bhi,Blo, each 128 rows x 64B (SW64) = 8KB -> 32KB.
// ---------------------------------------------------------------------------
#define STAGE_BYTES 32768
#define SMEM_BYTES  (2 * STAGE_BYTES)
#define NCHUNK      16

__global__ __launch_bounds__(256, 2)
void score_gemm_mma(const float* __restrict__ V) {
    extern __shared__ char sm[];
    const uint32_t uBase = smem_u32(sm);

    const int tid = threadIdx.x;
    const int w = tid >> 5;
    const int lane = tid & 31;
    const int rowBase = blockIdx.x * 128;
    const int colBase = blockIdx.y * 128;
    const int b = rowBase / NS;

    const int wm = (w & 1) * 64;
    const int wn = (w >> 1) * 32;

    // cp.async per-thread indices: 2 x 16B per tile per chunk
    const int row0 = tid >> 2;            // 0..63
    const int g0 = tid & 3;
    const uint32_t so0 = sw64(row0 * 64 + g0 * 16);
    const uint32_t so1 = sw64((row0 + 64) * 64 + g0 * 16);
    const size_t aoff0 = (size_t)(rowBase + row0) * ND + g0 * 8;
    const size_t aoff1 = aoff0 + (size_t)64 * ND;
    const size_t boff0 = (size_t)(colBase + row0) * ND + g0 * 8;
    const size_t boff1 = boff0 + (size_t)64 * ND;

    // ldmatrix lane addressing (SW64: xor bits 4..5 = (row>>1)&3)
    const int aKH = (lane >> 4) * 16;
    const int bKH = ((lane >> 3) & 1) * 16;
    int pA[4], xA[4];
#pragma unroll
    for (int mt = 0; mt < 4; mt++) {
        int r = wm + mt * 16 + (lane & 15);
        pA[mt] = r * 64;
        xA[mt] = ((r >> 1) & 3) << 4;
    }
    int pB[2], xB[2];
#pragma unroll
    for (int nt2 = 0; nt2 < 2; nt2++) {
        int r = wn + nt2 * 16 + (lane & 7) + ((lane >> 4) << 3);
        pB[nt2] = r * 64;
        xB[nt2] = ((r >> 1) & 3) << 4;
    }

    float c[4][4][4];
#pragma unroll
    for (int i = 0; i < 4; i++)
#pragma unroll
        for (int j = 0; j < 4; j++)
#pragma unroll
            for (int k = 0; k < 4; k++) c[i][j][k] = 0.f;

    // ---- pipeline ----
    // issue chunk 0
    {
        const uint32_t sb = uBase;
        cp16(sb + so0, g_enc_hi + aoff0);
        cp16(sb + so1, g_enc_hi + aoff1);
        cp16(sb + 8192 + so0, g_enc_lo + aoff0);
        cp16(sb + 8192 + so1, g_enc_lo + aoff1);
        cp16(sb + 16384 + so0, g_w1t_hi + boff0);
        cp16(sb + 16384 + so1, g_w1t_hi + boff1);
        cp16(sb + 24576 + so0, g_w1t_lo + boff0);
        cp16(sb + 24576 + so1, g_w1t_lo + boff1);
        CP_COMMIT();
    }

    for (int cc = 0; cc < NCHUNK; cc++) {
        if (cc + 1 < NCHUNK) {
            const int k1 = (cc + 1) * 32;
            const uint32_t sb = uBase + ((cc + 1) & 1) * STAGE_BYTES;
            cp16(sb + so0, g_enc_hi + aoff0 + k1);
            cp16(sb + so1, g_enc_hi + aoff1 + k1);
            cp16(sb + 8192 + so0, g_enc_lo + aoff0 + k1);
            cp16(sb + 8192 + so1, g_enc_lo + aoff1 + k1);
            cp16(sb + 16384 + so0, g_w1t_hi + boff0 + k1);
            cp16(sb + 16384 + so1, g_w1t_hi + boff1 + k1);
            cp16(sb + 24576 + so0, g_w1t_lo + boff0 + k1);
            cp16(sb + 24576 + so1, g_w1t_lo + boff1 + k1);
            CP_COMMIT();
            CP_WAIT1();
        } else {
            CP_WAIT0();
        }
        __syncthreads();

        const uint32_t uAh = uBase + (cc & 1) * STAGE_BYTES;
        const uint32_t uAl = uAh + 8192;
        const uint32_t uBh = uAh + 16384;
        const uint32_t uBl = uAh + 24576;

#pragma unroll
        for (int s = 0; s < 2; s++) {
            const int kb = s * 32;
            uint32_t ah[4][4], al[4][4], bh[2][4], bl[2][4];
#pragma unroll
            for (int mt = 0; mt < 4; mt++)
                ldmx4(ah[mt], uAh + pA[mt] + ((kb + aKH) ^ xA[mt]));
#pragma unroll
            for (int nt2 = 0; nt2 < 2; nt2++)
                ldmx4(bh[nt2], uBh + pB[nt2] + ((kb + bKH) ^ xB[nt2]));
#pragma unroll
            for (int mt = 0; mt < 4; mt++)
#pragma unroll
                for (int nt = 0; nt < 4; nt++)
                    mma_bf16(c[mt][nt], ah[mt], &bh[nt >> 1][(nt & 1) * 2]);

#pragma unroll
            for (int nt2 = 0; nt2 < 2; nt2++)
                ldmx4(bl[nt2], uBl + pB[nt2] + ((kb + bKH) ^ xB[nt2]));
#pragma unroll
            for (int mt = 0; mt < 4; mt++)
#pragma unroll
                for (int nt = 0; nt < 4; nt++)
                    mma_bf16(c[mt][nt], ah[mt], &bl[nt >> 1][(nt & 1) * 2]);

#pragma unroll
            for (int mt = 0; mt < 4; mt++)
                ldmx4(al[mt], uAl + pA[mt] + ((kb + aKH) ^ xA[mt]));
#pragma unroll
            for (int mt = 0; mt < 4; mt++)
#pragma unroll
                for (int nt = 0; nt < 4; nt++)
                    mma_bf16(c[mt][nt], al[mt], &bh[nt >> 1][(nt & 1) * 2]);
        }
        __syncthreads();
    }

    // ---- epilogue: tanh + V-dot, lane reduce, atomic per row ----
    float dv[8], vv[8];
#pragma unroll
    for (int nt = 0; nt < 4; nt++) {
#pragma unroll
        for (int i = 0; i < 2; i++) {
            int col = colBase + wn + nt * 8 + (lane & 3) * 2 + i;
            dv[nt * 2 + i] = g_decp[b * NU + col];
            vv[nt * 2 + i] = V[col];
        }
    }
    float rowsum[4][2];
#pragma unroll
    for (int mt = 0; mt < 4; mt++) {
#pragma unroll
        for (int h = 0; h < 2; h++) {
            float s = 0.f;
#pragma unroll
            for (int nt = 0; nt < 4; nt++) {
#pragma unroll
                for (int i = 0; i < 2; i++) {
                    float x = c[mt][nt][h * 2 + i] + dv[nt * 2 + i];
                    s += tanh_fast(x) * vv[nt * 2 + i];
                }
            }
            rowsum[mt][h] = s;
        }
    }
#pragma unroll
    for (int mt = 0; mt < 4; mt++) {
#pragma unroll
        for (int h = 0; h < 2; h++) {
            float s = rowsum[mt][h];
            s += __shfl_xor_sync(0xffffffffu, s, 1);
            s += __shfl_xor_sync(0xffffffffu, s, 2);
            rowsum[mt][h] = s;
        }
    }
    if ((lane & 3) == 0) {
#pragma unroll
        for (int mt = 0; mt < 4; mt++)
#pragma unroll
            for (int h = 0; h < 2; h++) {
                int r = rowBase + wm + mt * 16 + (lane >> 2) + h * 8;
                atomicAdd(&g_score[r], rowsum[mt][h]);
            }
    }
}

// ---------------------------------------------------------------------------
__global__ void softmax_kernel(float* __restrict__ out) {
    const int b = blockIdx.x;
    const int t = threadIdx.x;
    const float* sc = g_score + b * NS;
    __shared__ float redbuf[32];
    __shared__ float s_max, s_sum;

    float v[4];
    float m = -3.4e38f;
#pragma unroll
    for (int i = 0; i < 4; i++) { v[i] = sc[t + i * 1024]; m = fmaxf(m, v[i]); }
#pragma unroll
    for (int o = 16; o > 0; o >>= 1) m = fmaxf(m, __shfl_xor_sync(0xffffffffu, m, o));
    if ((t & 31) == 0) redbuf[t >> 5] = m;
    __syncthreads();
    if (t < 32) {
        float x = redbuf[t];
#pragma unroll
        for (int o = 16; o > 0; o >>= 1) x = fmaxf(x, __shfl_xor_sync(0xffffffffu, x, o));
        if (t == 0) s_max = x;
    }
    __syncthreads();
    const float bm = s_max;
    float e[4], s = 0.f;
#pragma unroll
    for (int i = 0; i < 4; i++) { e[i] = __expf(v[i] - bm); s += e[i]; }
#pragma unroll
    for (int o = 16; o > 0; o >>= 1) s += __shfl_xor_sync(0xffffffffu, s, o);
    if ((t & 31) == 0) redbuf[t >> 5] = s;
    __syncthreads();
    if (t < 32) {
        float x = redbuf[t];
#pragma unroll
        for (int o = 16; o > 0; o >>= 1) x += __shfl_xor_sync(0xffffffffu, x, o);
        if (t == 0) s_sum = x;
    }
    __syncthreads();
    const float inv = 1.0f / s_sum;
#pragma unroll
    for (int i = 0; i < 4; i++) out[NB * ND + b * NS + t + i * 1024] = e[i] * inv;
}

__global__ void ctx_part_kernel(const float* __restrict__ enc, const float* __restrict__ out) {
    const int b = blockIdx.x >> 5;
    const int chunk = blockIdx.x & 31;
    const int d = threadIdx.x;
    __shared__ float ws[128];
    const float* w = out + NB * ND + b * NS + chunk * 128;
    if (d < 128) ws[d] = w[d];
    __syncthreads();
    const float* ep = enc + ((size_t)(b * NS + chunk * 128)) * ND + d;
    float acc = 0.f;
#pragma unroll 8
    for (int s = 0; s < 128; s++) acc += ws[s] * ep[(size_t)s * ND];
    g_ctx_part[((size_t)chunk * NB + b) * ND + d] = acc;
}

__global__ void ctx_reduce_kernel(float* __restrict__ out) {
    const int b = blockIdx.x;
    const int d = threadIdx.x;
    float acc = 0.f;
#pragma unroll
    for (int c = 0; c < 32; c++) acc += g_ctx_part[((size_t)c * NB + b) * ND + d];
    out[b * ND + d] = acc;
}

// ---------------------------------------------------------------------------
extern "C" void kernel_launch(void* const* d_in, const int* in_sizes, int n_in,
                              void* d_out, int out_size) {
    const float* enc = (const float*)d_in[0];
    const float* dec = (const float*)d_in[1];
    const float* W1  = (const float*)d_in[2];
    const float* b1  = (const float*)d_in[3];
    const float* W2  = (const float*)d_in[4];
    const float* b2  = (const float*)d_in[5];
    const float* V   = (const float*)d_in[6];
    const float* bv  = (const float*)d_in[7];
    float* out = (float*)d_out;

    cudaFuncSetAttribute(score_gemm_mma, cudaFuncAttributeMaxDynamicSharedMemorySize,
                         SMEM_BYTES);

    convert_enc_kernel<<<(size_t)NM * ND / (256 * 8), 256>>>(enc);
    convert_w1_kernel<<<NU * ND / 256, 256>>>(W1);
    init_score_kernel<<<(NB * NS + 255) / 256, 256>>>(bv);
    decp_kernel<<<NB, NU>>>(dec, W2, b1, b2);
    score_gemm_mma<<<dim3(NM / 128, NU / 128), 256, SMEM_BYTES>>>(V);
    softmax_kernel<<<NB, 1024>>>(out);
    ctx_part_kernel<<<NB * 32, ND>>>(enc, out);
    ctx_reduce_kernel<<<NB, ND>>>(out);
}